// round 9
// baseline (speedup 1.0000x reference)
#include <cuda_runtime.h>
#include <cuda_bf16.h>

#define OUT_CH  128
#define EPB     16           // edges per block
#define THREADS 256
#define NW      (THREADS/32) // 8 warps

// Block b owns edges [b*EPB, (b+1)*EPB).
//  - 17 boundaries via windowed warp-parallel lower_bound, interleaved PAIRS
//    per warp (warp w: {w, w+8}; warp 0 additionally 16) so the block's
//    critical path is ~one search (3 rounds + verify, chains overlap).
//    Window = guess +-8192, verified + geometrically expanded -> correct for
//    any sorted input.
//  - stream ONLY tokens (8 MB total): 8-token chunks, fast path = two
//    256-entry packed-u64 LUT lookups; boundary state = two scalars.
//  - accumulate in a register; flush to s_hist[edge] via 64-bit smem
//    atomicAdd only on edge transitions (~1-2 per thread).
//  - epilogue: warp w writes edges w and w+8 (embedding regs reused).
__global__ void __launch_bounds__(THREADS)
fused_edge_mean(const int* __restrict__ tokens,
                const int* __restrict__ segs,
                const float* __restrict__ emb,   // [4][128]
                float* __restrict__ out,         // [E][128]
                int total_tokens,
                int n_edges) {
    __shared__ unsigned long long s_hist[EPB];   // packed: count(t) in field t
    __shared__ unsigned long long s_lut[256];
    __shared__ int s_bound[EPB + 1];

    const int tid  = threadIdx.x;
    const int lane = tid & 31;
    const int wid  = tid >> 5;
    const int e0   = blockIdx.x * EPB;

    // LUT: entry i = sum over its four 2-bit fields t of (1 << t*16)
    {
        const int t0 = tid & 3, t1 = (tid >> 2) & 3,
                  t2 = (tid >> 4) & 3, t3 = (tid >> 6) & 3;
        s_lut[tid] = (1ull << (t0 * 16)) + (1ull << (t1 * 16))
                   + (1ull << (t2 * 16)) + (1ull << (t3 * 16));
    }
    if (tid < EPB) s_hist[tid] = 0ull;

    // ---- interleaved searches: warp w -> {w, w+8}; warp 0 also 16 ----
    {
        const int nslots = (wid == 0) ? 3 : 2;
        int tg[3], lo[3], hi[3];
        tg[0] = e0 + wid; tg[1] = e0 + wid + 8; tg[2] = e0 + EPB;

#pragma unroll
        for (int s = 0; s < 3; s++) {
            if (s >= nslots) { lo[s] = 0; hi[s] = 0; continue; }
            const long long g = (long long)tg[s] * total_tokens / n_edges;
            int W = 8192;
            for (;;) {
                int l = (int)(g - W); if (l < 0) l = 0;
                int h = (int)(g + W); if (h > total_tokens) h = total_tokens;
                const bool ok_lo = (l == 0) || (__ldg(&segs[l - 1]) < tg[s]);
                const bool ok_hi = (h >= total_tokens) || (__ldg(&segs[h]) >= tg[s]);
                if (ok_lo && ok_hi) { lo[s] = l; hi[s] = h; break; }
                W <<= 3;
                if (W >= total_tokens) { lo[s] = 0; hi[s] = total_tokens; break; }
            }
        }
        // interleaved 32-ary lower_bound rounds (lo/hi uniform across lanes)
        while ((hi[0] > lo[0]) | (hi[1] > lo[1]) | (hi[2] > lo[2])) {
            int v[3], st[3];
#pragma unroll
            for (int s = 0; s < 3; s++) {
                v[s] = 0x7FFFFFFF; st[s] = 0;
                if (hi[s] > lo[s]) {
                    st[s] = (hi[s] - lo[s] + 31) >> 5;
                    const int idx = lo[s] + lane * st[s];
                    if (idx < hi[s]) v[s] = __ldg(&segs[idx]);
                }
            }
#pragma unroll
            for (int s = 0; s < 3; s++) {
                if (hi[s] > lo[s]) {
                    const unsigned m = __ballot_sync(0xFFFFFFFFu, v[s] < tg[s]);
                    const int cnt = __popc(m);     // sorted -> contiguous mask
                    const int nlo = cnt ? lo[s] + (cnt - 1) * st[s] + 1 : lo[s];
                    const int nhi = (cnt < 32) ? min(hi[s], lo[s] + cnt * st[s]) : hi[s];
                    lo[s] = nlo; hi[s] = max(nhi, nlo);
                }
            }
        }
        if (lane == 0) {
            s_bound[wid]     = lo[0];
            s_bound[wid + 8] = lo[1];
            if (wid == 0) s_bound[EPB] = lo[2];
        }
    }
    __syncthreads();

    const int start = s_bound[0];
    const int end   = s_bound[EPB];

    // ---- stream tokens only: 8-token chunks (2 x int4) ----
    const int4* tokens4 = (const int4*)tokens;
    const int p0 = start >> 3;
    const int p1 = (end + 7) >> 3;            // T is a multiple of 8

    int le = -1;                              // current local edge
    {
        const int idx0 = (p0 + tid) << 3;
#pragma unroll
        for (int k = 0; k <= EPB; k++) le += (s_bound[k] <= idx0);
    }
    int nextb = (le < 0) ? start : ((le < EPB) ? s_bound[le + 1] : 0x7FFFFFFF);

    unsigned long long acc = 0ull;

    for (int p = p0 + tid; p < p1; p += THREADS) {
        const int4 ta = tokens4[2 * p];
        const int4 tb = tokens4[2 * p + 1];
        const int base = p << 3;

        if (base + 8 <= nextb) {
            // fast path: whole chunk inside current region (tokens are 0..3)
            const int ia = ta.x + (ta.y << 2) + (ta.z << 4) + (ta.w << 6);
            const int ib = tb.x + (tb.y << 2) + (tb.z << 4) + (tb.w << 6);
            acc += s_lut[ia] + s_lut[ib];
        } else {
            const int tt[8] = {ta.x, ta.y, ta.z, ta.w, tb.x, tb.y, tb.z, tb.w};
#pragma unroll
            for (int k = 0; k < 8; k++) {
                const int idx = base + k;
                if (idx >= nextb) {           // edge transition (rare)
                    if (acc && (unsigned)le < EPB)
                        atomicAdd(&s_hist[le], acc);
                    acc = 0ull;
                    le++;
                    while (le < EPB && idx >= s_bound[le + 1]) le++;
                    nextb = (le < EPB) ? s_bound[le + 1] : 0x7FFFFFFF;
                }
                acc += 1ull << (tt[k] * 16);
            }
        }
    }
    if (acc && (unsigned)le < EPB) atomicAdd(&s_hist[le], acc);
    __syncthreads();

    // ---- epilogue: warp w writes edges e0+w and e0+w+8 ----
    const int d = lane * 4;
    const float4 e0v = *(const float4*)(emb + 0 * OUT_CH + d);
    const float4 e1v = *(const float4*)(emb + 1 * OUT_CH + d);
    const float4 e2v = *(const float4*)(emb + 2 * OUT_CH + d);
    const float4 e3v = *(const float4*)(emb + 3 * OUT_CH + d);

#pragma unroll
    for (int r = 0; r < 2; r++) {
        const int leo = wid + r * NW;
        const int e   = e0 + leo;
        if (e < n_edges) {
            const unsigned long long h = s_hist[leo];   // broadcast LDS
            const float f0 = (float)((unsigned)(h      ) & 0xFFFFu);
            const float f1 = (float)((unsigned)(h >> 16) & 0xFFFFu);
            const float f2 = (float)((unsigned)(h >> 32) & 0xFFFFu);
            const float f3 = (float)((unsigned)(h >> 48) & 0xFFFFu);
            const float inv = 1.0f / fmaxf(f0 + f1 + f2 + f3, 1.0f);

            float4 rv;
            rv.x = (f0 * e0v.x + f1 * e1v.x + f2 * e2v.x + f3 * e3v.x) * inv;
            rv.y = (f0 * e0v.y + f1 * e1v.y + f2 * e2v.y + f3 * e3v.y) * inv;
            rv.z = (f0 * e0v.z + f1 * e1v.z + f2 * e2v.z + f3 * e3v.z) * inv;
            rv.w = (f0 * e0v.w + f1 * e1v.w + f2 * e2v.w + f3 * e3v.w) * inv;

            *(float4*)(out + (long long)e * OUT_CH + d) = rv;
        }
    }
}

extern "C" void kernel_launch(void* const* d_in, const int* in_sizes, int n_in,
                              void* d_out, int out_size) {
    // Inputs: 0 overlap_similarity f32[E], 1 overlap_length f32[E],
    //         2 tokens i32[T], 3 segment_ids i32[T], 4 embedding f32[4*128],
    //         5 n_edges
    const int*   tokens = (const int*)d_in[2];
    const int*   segs   = (const int*)d_in[3];
    const float* emb    = (const float*)d_in[4];
    float*       out    = (float*)d_out;

    const int total_tokens = in_sizes[2];
    const int n_edges      = out_size / OUT_CH;

    const int blocks = (n_edges + EPB - 1) / EPB;   // 512
    fused_edge_mean<<<blocks, THREADS>>>(tokens, segs, emb, out,
                                         total_tokens, n_edges);
}